// round 1
// baseline (speedup 1.0000x reference)
#include <cuda_runtime.h>

#define N_NODES 1000000
#define E_EDGES 32000000
#define KH 5            // hops incl. identity
#define NHOP 4          // propagation rounds
#define OUTF 64
#define BN_EPS 1e-5f

// ---- scratch (module-static, allocation-free) ----
__device__ float g_feat[NHOP][N_NODES];   // hop results 1..4 (16 MB)
__device__ float g_Wp[OUTF * KH];          // feature-centered weights W'
__device__ float g_bp[OUTF];               // centered bias b'
__device__ float g_Wmean[KH];
__device__ float g_bw[KH];                 // sum_f b'[f] * W'[f,k]
__device__ float g_G[KH * KH];             // Gram: sum_f W'[f,k] W'[f,l]
__device__ float g_b2;                     // sum_f b'^2
__device__ float g_bmean;

// ---- zero the hop buffers (must happen every launch: scatter-add target) ----
__global__ void __launch_bounds__(256) zero_kernel() {
    int i = blockIdx.x * blockDim.x + threadIdx.x;
    float4* p = reinterpret_cast<float4*>(&g_feat[0][0]);
    if (i < (NHOP * N_NODES) / 4) p[i] = make_float4(0.f, 0.f, 0.f, 0.f);
}

// ---- one SpMV round: nxt[dst] += cur[src] * w, 4 edges/thread ----
__global__ void __launch_bounds__(256) prop_kernel(
    const int4* __restrict__ src4, const int4* __restrict__ dst4,
    const float4* __restrict__ w4, const float* __restrict__ x, int round)
{
    const float* __restrict__ cur = (round == 0) ? x : g_feat[round - 1];
    float* nxt = g_feat[round];

    int i = blockIdx.x * blockDim.x + threadIdx.x;   // < E/4 exactly
    int4  s = src4[i];
    int4  d = dst4[i];
    float4 w = w4[i];

    float v0 = __ldg(&cur[s.x]) * w.x;
    float v1 = __ldg(&cur[s.y]) * w.y;
    float v2 = __ldg(&cur[s.z]) * w.z;
    float v3 = __ldg(&cur[s.w]) * w.w;

    atomicAdd(&nxt[d.x], v0);
    atomicAdd(&nxt[d.y], v1);
    atomicAdd(&nxt[d.z], v2);
    atomicAdd(&nxt[d.w], v3);
}

// ---- tiny precompute of centered weights + quadratic-form constants ----
__global__ void precompute_kernel(const float* __restrict__ weight,
                                  const float* __restrict__ bias)
{
    __shared__ float sW[OUTF * KH];
    __shared__ float sb[OUTF];
    int t = threadIdx.x;   // 64 threads
    sb[t] = bias[t];
#pragma unroll
    for (int k = 0; k < KH; k++) sW[t * KH + k] = weight[t * KH + k];
    __syncthreads();
    if (t == 0) {
        float bm = 0.f;
        for (int f = 0; f < OUTF; f++) bm += sb[f];
        bm *= (1.f / OUTF);
        float wm[KH] = {0.f, 0.f, 0.f, 0.f, 0.f};
        for (int f = 0; f < OUTF; f++)
            for (int k = 0; k < KH; k++) wm[k] += sW[f * KH + k];
        for (int k = 0; k < KH; k++) wm[k] *= (1.f / OUTF);

        g_bmean = bm;
        for (int k = 0; k < KH; k++) g_Wmean[k] = wm[k];

        float b2 = 0.f;
        float bw[KH] = {0.f, 0.f, 0.f, 0.f, 0.f};
        float G[KH * KH];
        for (int i = 0; i < KH * KH; i++) G[i] = 0.f;

        for (int f = 0; f < OUTF; f++) {
            float bp = sb[f] - bm;
            g_bp[f] = bp;
            b2 += bp * bp;
            float wp[KH];
            for (int k = 0; k < KH; k++) {
                wp[k] = sW[f * KH + k] - wm[k];
                g_Wp[f * KH + k] = wp[k];
                bw[k] += bp * wp[k];
            }
            for (int k = 0; k < KH; k++)
                for (int l = 0; l < KH; l++) G[k * KH + l] += wp[k] * wp[l];
        }
        g_b2 = b2;
        for (int k = 0; k < KH; k++) g_bw[k] = bw[k];
        for (int i = 0; i < KH * KH; i++) g_G[i] = G[i];
    }
}

// ---- fused linear + BN(training) + affine. One warp per node. ----
__global__ void __launch_bounds__(256) final_kernel(
    const float* __restrict__ x, const float* __restrict__ gamma,
    const float* __restrict__ beta, float* __restrict__ out)
{
    __shared__ float sWp[OUTF * KH];
    __shared__ float sbp[OUTF];
    __shared__ float sWm[KH], sbw[KH], sG[KH * KH];
    __shared__ float sb2, sbm;

    int t = threadIdx.x;
    if (t < 64) {
        sbp[t] = g_bp[t];
#pragma unroll
        for (int k = 0; k < KH; k++) sWp[t * KH + k] = g_Wp[t * KH + k];
    } else if (t < 69) {
        sWm[t - 64] = g_Wmean[t - 64];
    } else if (t < 74) {
        sbw[t - 69] = g_bw[t - 69];
    } else if (t < 99) {
        sG[t - 74] = g_G[t - 74];
    } else if (t == 99) {
        sb2 = g_b2;
        sbm = g_bmean;
    }
    __syncthreads();

    int warp = t >> 5;
    int lane = t & 31;
    int n = blockIdx.x * 8 + warp;   // N divisible by 8

    float c[KH];
    c[0] = __ldg(&x[n]);
    c[1] = g_feat[0][n];
    c[2] = g_feat[1][n];
    c[3] = g_feat[2][n];
    c[4] = g_feat[3][n];

    // per-node mean & variance over the 64 features (analytic quadratic form)
    float mu = sbm;
#pragma unroll
    for (int k = 0; k < KH; k++) mu += c[k] * sWm[k];

    float ss = sb2;
#pragma unroll
    for (int k = 0; k < KH; k++) ss += 2.f * c[k] * sbw[k];
#pragma unroll
    for (int k = 0; k < KH; k++) {
#pragma unroll
        for (int l = 0; l < KH; l++) ss += c[k] * c[l] * sG[k * KH + l];
    }
    float var = ss * (1.f / OUTF);

    float a  = __ldg(&gamma[n]) * rsqrtf(var + BN_EPS);
    float be = __ldg(&beta[n]);

    size_t base = (size_t)n * OUTF;
#pragma unroll
    for (int half = 0; half < 2; half++) {
        int f = lane + half * 32;
        float z = sbp[f];
#pragma unroll
        for (int k = 0; k < KH; k++) z += c[k] * sWp[f * KH + k];
        out[base + f] = a * z + be;
    }
}

extern "C" void kernel_launch(void* const* d_in, const int* in_sizes, int n_in,
                              void* d_out, int out_size)
{
    const float* x      = (const float*)d_in[0];
    const int*   ei     = (const int*)  d_in[1];   // [2, E]
    const float* ew     = (const float*)d_in[2];
    const float* weight = (const float*)d_in[3];   // [64,5,1]
    const float* bias   = (const float*)d_in[4];
    const float* gamma  = (const float*)d_in[5];
    const float* beta   = (const float*)d_in[6];
    float* out = (float*)d_out;

    const int E = in_sizes[2];            // 32,000,000
    const int4*   src4 = (const int4*)ei;
    const int4*   dst4 = (const int4*)(ei + E);
    const float4* w4   = (const float4*)ew;

    zero_kernel<<<(NHOP * N_NODES / 4 + 255) / 256, 256>>>();

    int prop_blocks = (E / 4) / 256;      // 31250, exact
    for (int r = 0; r < NHOP; r++)
        prop_kernel<<<prop_blocks, 256>>>(src4, dst4, w4, x, r);

    precompute_kernel<<<1, 64>>>(weight, bias);
    final_kernel<<<N_NODES / 8, 256>>>(x, gamma, beta, out);
}